// round 10
// baseline (speedup 1.0000x reference)
#include <cuda_runtime.h>
#include <cuda_fp16.h>
#include <math.h>
#include <cstdint>

#define BB 64
#define NN 128
#define XS 9   // words per edge row in s_x1 (stride padding)

// scratch for intermediate coors/vel between layers (no allocs allowed)
__device__ float g_c0[BB*NN*2];
__device__ float g_v0[BB*NN*2];
__device__ float g_c1[BB*NN*2];
__device__ float g_v1[BB*NN*2];

union F2U { float2 f; unsigned long long u; };
union H2U { __half2 h; uint32_t u; };

__device__ __forceinline__ float2 ffma2(float2 a, float2 b, float2 c) {
    F2U A, B, C, R;
    A.f = a; B.f = b; C.f = c;
    asm("fma.rn.f32x2 %0, %1, %2, %3;" : "=l"(R.u) : "l"(A.u), "l"(B.u), "l"(C.u));
    return R.f;
}
__device__ __forceinline__ float2 fmul2(float2 a, float2 b) {
    F2U A, B, R;
    A.f = a; B.f = b;
    asm("mul.rn.f32x2 %0, %1, %2;" : "=l"(R.u) : "l"(A.u), "l"(B.u));
    return R.f;
}

// ---- packed f16x2 silu machinery ----
__device__ __forceinline__ uint32_t f2_to_h2(float2 v) {
    uint32_t r;  // d.hi = first src, d.lo = second src
    asm("cvt.rn.f16x2.f32 %0, %1, %2;" : "=r"(r) : "f"(v.y), "f"(v.x));
    return r;
}
__device__ __forceinline__ float2 h2_to_f2(uint32_t x) {
    H2U c; c.u = x;
    return __half22float2(c.h);
}
__device__ __forceinline__ uint32_t tanh_h2(uint32_t x) {
    uint32_t r;
    asm("tanh.approx.f16x2 %0, %1;" : "=r"(r) : "r"(x));
    return r;
}
__device__ __forceinline__ uint32_t hfma2u(uint32_t a, uint32_t b, uint32_t c) {
    H2U A, B, C, R;
    A.u = a; B.u = b; C.u = c;
    R.h = __hfma2(A.h, B.h, C.h);
    return R.u;
}
__device__ __forceinline__ uint32_t hmul2u(uint32_t a, uint32_t b) {
    H2U A, B, R;
    A.u = a; B.u = b;
    R.h = __hmul2(A.h, B.h);
    return R.u;
}
// h = x/2 packed f16x2 -> silu(x) = h + h*tanh(h), all f16x2
__device__ __forceinline__ uint32_t silu_h2_pre(uint32_t h) {
    return hfma2u(h, tanh_h2(h), h);
}
// full silu on packed x
__device__ __forceinline__ uint32_t silu_h2(uint32_t x) {
    H2U half_c; half_c.h = __floats2half2_rn(0.5f, 0.5f);
    return silu_h2_pre(hmul2u(x, half_c.u));
}

__device__ __forceinline__ float seluf(float x) {
    const float scale = 1.0507009873554805f;
    const float alpha = 1.6732632423543772f;
    return x > 0.0f ? scale * x : scale * alpha * expm1f(x);
}

__device__ __forceinline__ uint32_t pack_h2s(float a, float b) {
    H2U c; c.h = __floats2half2_rn(a, b);
    return c.u;
}

// mma.m16n8k16 with C operand (bias folding)
__device__ __forceinline__ void mma16816c(float& d0, float& d1, float& d2, float& d3,
                                          uint32_t a0, uint32_t a1, uint32_t a2, uint32_t a3,
                                          uint32_t b0, uint32_t b1,
                                          float c0, float c1, float c2, float c3) {
    asm("mma.sync.aligned.m16n8k16.row.col.f32.f16.f16.f32 "
        "{%0,%1,%2,%3}, {%4,%5,%6,%7}, {%8,%9}, {%10,%11,%12,%13};"
        : "=f"(d0), "=f"(d1), "=f"(d2), "=f"(d3)
        : "r"(a0), "r"(a1), "r"(a2), "r"(a3), "r"(b0), "r"(b1),
          "f"(c0), "f"(c1), "f"(c2), "f"(c3));
}

__global__ __launch_bounds__(128, 5)
void egnn_layer_kernel(const float* __restrict__ t,
                       const float* __restrict__ cin,
                       const float* __restrict__ vin,
                       float* __restrict__ cout,
                       float* __restrict__ vout,
                       const float* __restrict__ We1,
                       const float* __restrict__ be1,
                       const float* __restrict__ We2,
                       const float* __restrict__ be2,
                       const float* __restrict__ Wc1,
                       const float* __restrict__ bc1,
                       const float* __restrict__ Wc2,
                       const float* __restrict__ bc2,
                       const float* __restrict__ Wv,
                       const float* __restrict__ bv,
                       int l)
{
    __shared__ float4 sUVp[8];        // {u2c,u2c1,v2c,v2c1} x0.5
    __shared__ float4 sWCp[8];        // {w2c,w2c1,(c+be1)2c,(c+be1)2c1} x0.5
    __shared__ float2 sbe2p[8];       // {0.5be2[2c],0.5be2[2c+1]}
    __shared__ float  sWe2raw[256];   // 0.5*We2 [k*16+n]
    __shared__ float  sWc1raw[1024];  // 0.5*Wc1 [k*64+n]
    __shared__ float4 sbw3[32];       // [c]={0.5bc1[2c],0.5bc1[2c+1],Wc2[2c],Wc2[2c+1]}
    __shared__ float2 scj2[NN];
    __shared__ float  stj[NN];
    __shared__ uint32_t s_x1[4 * NN * XS];   // per-warp x1 tiles, f16x2 [edge][k-pair]

    const int tid   = threadIdx.x;
    const int wid   = tid >> 5;
    const int ln    = tid & 31;
    const int bb    = blockIdx.x >> 5;
    const int ibase = (blockIdx.x & 31) * 4;
    const int i     = ibase + wid;

    // ---- staging ----
    const float* we1 = We1 + l * 128;
    if (tid < 8) {
        int c0 = 2 * tid, c1 = 2 * tid + 1;
        float u0 = 0.5f * (we1[c0] + we1[16 + c0] + we1[32 + c0]);
        float u1 = 0.5f * (we1[c1] + we1[16 + c1] + we1[32 + c1]);
        float v0 = 0.5f * (we1[48 + c0] + we1[64 + c0] + we1[80 + c0]);
        float v1 = 0.5f * (we1[48 + c1] + we1[64 + c1] + we1[80 + c1]);
        float w0 = 0.5f * we1[96 + c0];
        float w1 = 0.5f * we1[96 + c1];
        float k0 = 0.5f * (we1[112 + c0] + be1[l * 16 + c0]);
        float k1 = 0.5f * (we1[112 + c1] + be1[l * 16 + c1]);
        sUVp[tid] = make_float4(u0, u1, v0, v1);
        sWCp[tid] = make_float4(w0, w1, k0, k1);
        sbe2p[tid] = make_float2(0.5f * be2[l * 16 + c0], 0.5f * be2[l * 16 + c1]);
    } else if (tid < 40) {
        int k = tid - 8;
        sbw3[k] = make_float4(0.5f * bc1[l * 64 + 2 * k], 0.5f * bc1[l * 64 + 2 * k + 1],
                              Wc2[l * 64 + 2 * k],        Wc2[l * 64 + 2 * k + 1]);
    }
    #pragma unroll
    for (int idx = tid; idx < 256; idx += 128)
        sWe2raw[idx] = 0.5f * We2[l * 256 + idx];
    #pragma unroll
    for (int idx = tid; idx < 1024; idx += 128)
        sWc1raw[idx] = 0.5f * Wc1[l * 1024 + idx];
    {
        const float2* c2 = (const float2*)(cin + bb * NN * 2);
        scj2[tid] = c2[tid];
        stj[tid]  = t[bb * NN + tid];
    }
    __syncthreads();

    const float ti  = stj[i];
    const float2 ci = scj2[i];
    const float2 ti2 = make_float2(ti, ti);

    // ---- persistent B fragments ----
    const int p = ln & 3;
    const int g = ln >> 2;
    uint32_t b2f0[2], b2f1[2];
    #pragma unroll
    for (int nt = 0; nt < 2; ++nt) {
        int col = nt * 8 + g;
        b2f0[nt] = pack_h2s(sWe2raw[(2 * p) * 16 + col],     sWe2raw[(2 * p + 1) * 16 + col]);
        b2f1[nt] = pack_h2s(sWe2raw[(2 * p + 8) * 16 + col], sWe2raw[(2 * p + 9) * 16 + col]);
    }
    uint32_t bf0[8], bf1[8];
    #pragma unroll
    for (int nt = 0; nt < 8; ++nt) {
        int col = nt * 8 + g;
        bf0[nt] = pack_h2s(sWc1raw[(2 * p) * 64 + col],     sWc1raw[(2 * p + 1) * 64 + col]);
        bf1[nt] = pack_h2s(sWc1raw[(2 * p + 8) * 64 + col], sWc1raw[(2 * p + 9) * 64 + col]);
    }
    const float2 be2b0 = sbe2p[p];
    const float2 be2b1 = sbe2p[p + 4];

    // ---- phase 1: x1 (f32 matvec, f16x2 silu) -> f16 edge-major shared ----
    uint32_t* sx = s_x1 + wid * NN * XS;
    #pragma unroll
    for (int ee = 0; ee < 4; ++ee) {
        const int e = ln + 32 * ee;
        const float tj = stj[e];
        const float2 cj = scj2[e];
        const float dx = ci.x - cj.x;
        const float dy = ci.y - cj.y;
        const float d = fmaf(dx, dx, dy * dy);
        const float2 tj2 = make_float2(tj, tj);
        const float2 d2  = make_float2(d, d);
        #pragma unroll
        for (int cp = 0; cp < 8; ++cp) {
            float4 uv = sUVp[cp];
            float4 wc = sWCp[cp];
            float2 h = ffma2(ti2, make_float2(uv.x, uv.y),
                      ffma2(tj2, make_float2(uv.z, uv.w),
                      ffma2(d2,  make_float2(wc.x, wc.y),
                                 make_float2(wc.z, wc.w))));
            sx[e * XS + cp] = silu_h2_pre(f2_to_h2(h));
        }
    }
    __syncwarp();

    // ---- phase 2: 8 tiles of 16 edges ----
    const float bc2l = bc2[l];
    const float badd = (p == 0) ? bc2l : 0.0f;   // bias added once per row (lane p==0)
    float ax = 0.0f, ay = 0.0f;

    #pragma unroll
    for (int r = 0; r < 8; ++r) {
        const int elo = 16 * r + g;
        const int ehi = elo + 8;
        uint32_t a0 = sx[elo * XS + p];
        uint32_t a1 = sx[ehi * XS + p];
        uint32_t a2 = sx[elo * XS + p + 4];
        uint32_t a3 = sx[ehi * XS + p + 4];

        // MLP2: q = silu(silu(x1 @ We2 + be2)); f16x2 silu chain into MLP3 A frags
        uint32_t qa0, qa1, qa2, qa3;
        {
            float d0, d1, d2, d3;
            mma16816c(d0, d1, d2, d3, a0, a1, a2, a3, b2f0[0], b2f1[0],
                      be2b0.x, be2b0.y, be2b0.x, be2b0.y);
            qa0 = silu_h2(silu_h2_pre(f2_to_h2(make_float2(d0, d1))));
            qa1 = silu_h2(silu_h2_pre(f2_to_h2(make_float2(d2, d3))));
            mma16816c(d0, d1, d2, d3, a0, a1, a2, a3, b2f0[1], b2f1[1],
                      be2b1.x, be2b1.y, be2b1.x, be2b1.y);
            qa2 = silu_h2(silu_h2_pre(f2_to_h2(make_float2(d0, d1))));
            qa3 = silu_h2(silu_h2_pre(f2_to_h2(make_float2(d2, d3))));
        }

        // MLP3: h = silu(q @ Wc1 + bc1); partial row dot with Wc2 (f32 accum)
        float2 rs_lo = make_float2(0.0f, 0.0f);
        float2 rs_hi = make_float2(0.0f, 0.0f);
        #pragma unroll
        for (int nt = 0; nt < 8; ++nt) {
            float4 bw = sbw3[4 * nt + p];
            float d0, d1, d2, d3;
            mma16816c(d0, d1, d2, d3, qa0, qa1, qa2, qa3, bf0[nt], bf1[nt],
                      bw.x, bw.y, bw.x, bw.y);
            float2 wc = make_float2(bw.z, bw.w);
            float2 hlo = h2_to_f2(silu_h2_pre(f2_to_h2(make_float2(d0, d1))));
            float2 hhi = h2_to_f2(silu_h2_pre(f2_to_h2(make_float2(d2, d3))));
            rs_lo = ffma2(hlo, wc, rs_lo);
            rs_hi = ffma2(hhi, wc, rs_hi);
        }
        // deferred reduction: partial row sums feed agg directly (rel coords
        // uniform across the 4 lanes of a row; full sum happens in warp reduce)
        float sE  = rs_lo.x + rs_lo.y + badd;
        float sE8 = rs_hi.x + rs_hi.y + badd;
        float2 cjE  = scj2[elo];
        float2 cjE8 = scj2[ehi];
        ax += sE * (ci.x - cjE.x) + sE8 * (ci.x - cjE8.x);
        ay += sE * (ci.y - cjE.y) + sE8 * (ci.y - cjE8.y);
    }

    // ---- warp reduce + node update ----
    #pragma unroll
    for (int off = 16; off > 0; off >>= 1) {
        ax += __shfl_down_sync(0xFFFFFFFFu, ax, off);
        ay += __shfl_down_sync(0xFFFFFFFFu, ay, off);
    }
    if (ln == 0) {
        float wv  = Wv[l * 3] + Wv[l * 3 + 1] + Wv[l * 3 + 2];
        float phi = fmaf(ti, wv, bv[l]);
        float vx = vin[(bb * NN + i) * 2];
        float vy = vin[(bb * NN + i) * 2 + 1];
        float nvx = fmaf(phi, vx, ax);
        float nvy = fmaf(phi, vy, ay);
        float ncx = ci.x + nvx;
        float ncy = ci.y + nvy;
        cout[(bb * NN + i) * 2]     = seluf(ncx);
        cout[(bb * NN + i) * 2 + 1] = seluf(ncy);
        vout[(bb * NN + i) * 2]     = seluf(nvx);
        vout[(bb * NN + i) * 2 + 1] = seluf(nvy);
    }
}

__global__ void egnn_head_kernel(const float* __restrict__ cin,
                                 const float* __restrict__ vin,
                                 const float* __restrict__ Wconv1,
                                 const float* __restrict__ bconv1,
                                 const float* __restrict__ Wconv2,
                                 const float* __restrict__ bconv2,
                                 float* __restrict__ out)
{
    int idx = blockIdx.x * blockDim.x + threadIdx.x;
    if (idx >= BB * NN) return;

    float x0 = seluf(cin[idx * 2]);
    float x1 = seluf(cin[idx * 2 + 1]);
    float x2 = seluf(vin[idx * 2]);
    float x3 = seluf(vin[idx * 2 + 1]);

    float y0 = bconv2[0], y1 = bconv2[1], y2 = bconv2[2], y3 = bconv2[3];
    #pragma unroll
    for (int o = 0; o < 32; o++) {
        float h = bconv1[o];
        h = fmaf(x0, Wconv1[o * 4 + 0], h);
        h = fmaf(x1, Wconv1[o * 4 + 1], h);
        h = fmaf(x2, Wconv1[o * 4 + 2], h);
        h = fmaf(x3, Wconv1[o * 4 + 3], h);
        h = seluf(h);
        y0 = fmaf(h, Wconv2[0 * 32 + o], y0);
        y1 = fmaf(h, Wconv2[1 * 32 + o], y1);
        y2 = fmaf(h, Wconv2[2 * 32 + o], y2);
        y3 = fmaf(h, Wconv2[3 * 32 + o], y3);
    }
    out[idx * 2]                   = y0;
    out[idx * 2 + 1]               = y1;
    out[BB * NN * 2 + idx * 2]     = y2;
    out[BB * NN * 2 + idx * 2 + 1] = y3;
}

extern "C" void kernel_launch(void* const* d_in, const int* in_sizes, int n_in,
                              void* d_out, int out_size)
{
    const float* t      = (const float*)d_in[0];
    const float* coors  = (const float*)d_in[1];
    const float* vel    = (const float*)d_in[2];
    const float* We1    = (const float*)d_in[3];
    const float* be1    = (const float*)d_in[4];
    const float* We2    = (const float*)d_in[5];
    const float* be2    = (const float*)d_in[6];
    const float* Wc1    = (const float*)d_in[7];
    const float* bc1    = (const float*)d_in[8];
    const float* Wc2    = (const float*)d_in[9];
    const float* bc2    = (const float*)d_in[10];
    const float* Wv     = (const float*)d_in[11];
    const float* bv     = (const float*)d_in[12];
    const float* Wconv1 = (const float*)d_in[13];
    const float* bconv1 = (const float*)d_in[14];
    const float* Wconv2 = (const float*)d_in[15];
    const float* bconv2 = (const float*)d_in[16];
    float* out = (float*)d_out;

    float *c0, *v0, *c1, *v1;
    cudaGetSymbolAddress((void**)&c0, g_c0);
    cudaGetSymbolAddress((void**)&v0, g_v0);
    cudaGetSymbolAddress((void**)&c1, g_c1);
    cudaGetSymbolAddress((void**)&v1, g_v1);

    dim3 grid(BB * 32);   // 2048 blocks: (batch, group of 4 i's), warp-per-i
    dim3 blk(128);
    egnn_layer_kernel<<<grid, blk>>>(t, coors, vel, c0, v0,
                                     We1, be1, We2, be2, Wc1, bc1, Wc2, bc2,
                                     Wv, bv, 0);
    egnn_layer_kernel<<<grid, blk>>>(t, c0, v0, c1, v1,
                                     We1, be1, We2, be2, Wc1, bc1, Wc2, bc2,
                                     Wv, bv, 1);
    egnn_head_kernel<<<(BB * NN + 127) / 128, 128>>>(c1, v1, Wconv1, bconv1,
                                                     Wconv2, bconv2, out);
}

// round 12
// speedup vs baseline: 1.0240x; 1.0240x over previous
#include <cuda_runtime.h>
#include <cuda_fp16.h>
#include <math.h>
#include <cstdint>

#define BB 64
#define NN 128
#define XS 9   // words per edge row in s_x1 (stride padding)

// scratch for intermediate coors/vel between layers (no allocs allowed)
__device__ float g_c0[BB*NN*2];
__device__ float g_v0[BB*NN*2];
__device__ float g_c1[BB*NN*2];
__device__ float g_v1[BB*NN*2];

union F2U { float2 f; unsigned long long u; };
union H2U { __half2 h; uint32_t u; };

__device__ __forceinline__ float2 ffma2(float2 a, float2 b, float2 c) {
    F2U A, B, C, R;
    A.f = a; B.f = b; C.f = c;
    asm("fma.rn.f32x2 %0, %1, %2, %3;" : "=l"(R.u) : "l"(A.u), "l"(B.u), "l"(C.u));
    return R.f;
}

// ---- packed f16x2 silu machinery ----
__device__ __forceinline__ uint32_t f2_to_h2(float2 v) {
    uint32_t r;  // d.hi = first src, d.lo = second src
    asm("cvt.rn.f16x2.f32 %0, %1, %2;" : "=r"(r) : "f"(v.y), "f"(v.x));
    return r;
}
__device__ __forceinline__ uint32_t tanh_h2(uint32_t x) {
    uint32_t r;
    asm("tanh.approx.f16x2 %0, %1;" : "=r"(r) : "r"(x));
    return r;
}
__device__ __forceinline__ uint32_t hfma2u(uint32_t a, uint32_t b, uint32_t c) {
    H2U A, B, C, R;
    A.u = a; B.u = b; C.u = c;
    R.h = __hfma2(A.h, B.h, C.h);
    return R.u;
}
__device__ __forceinline__ uint32_t hmul2u(uint32_t a, uint32_t b) {
    H2U A, B, R;
    A.u = a; B.u = b;
    R.h = __hmul2(A.h, B.h);
    return R.u;
}
// h = x/2 packed f16x2 -> silu(x) = h + h*tanh(h), all f16x2
__device__ __forceinline__ uint32_t silu_h2_pre(uint32_t h) {
    return hfma2u(h, tanh_h2(h), h);
}
// full silu on packed x
__device__ __forceinline__ uint32_t silu_h2(uint32_t x) {
    H2U half_c; half_c.h = __floats2half2_rn(0.5f, 0.5f);
    return silu_h2_pre(hmul2u(x, half_c.u));
}

__device__ __forceinline__ float seluf(float x) {
    const float scale = 1.0507009873554805f;
    const float alpha = 1.6732632423543772f;
    return x > 0.0f ? scale * x : scale * alpha * expm1f(x);
}

__device__ __forceinline__ uint32_t pack_h2s(float a, float b) {
    H2U c; c.h = __floats2half2_rn(a, b);
    return c.u;
}
// residual after f16 rounding
__device__ __forceinline__ float h16res(float v) {
    return v - __half2float(__float2half_rn(v));
}

// mma.m16n8k16 with C operand (bias folding / accumulation chaining)
__device__ __forceinline__ void mma16816c(float& d0, float& d1, float& d2, float& d3,
                                          uint32_t a0, uint32_t a1, uint32_t a2, uint32_t a3,
                                          uint32_t b0, uint32_t b1,
                                          float c0, float c1, float c2, float c3) {
    asm("mma.sync.aligned.m16n8k16.row.col.f32.f16.f16.f32 "
        "{%0,%1,%2,%3}, {%4,%5,%6,%7}, {%8,%9}, {%10,%11,%12,%13};"
        : "=f"(d0), "=f"(d1), "=f"(d2), "=f"(d3)
        : "r"(a0), "r"(a1), "r"(a2), "r"(a3), "r"(b0), "r"(b1),
          "f"(c0), "f"(c1), "f"(c2), "f"(c3));
}

__global__ __launch_bounds__(128, 5)
void egnn_layer_kernel(const float* __restrict__ t,
                       const float* __restrict__ cin,
                       const float* __restrict__ vin,
                       float* __restrict__ cout,
                       float* __restrict__ vout,
                       const float* __restrict__ We1,
                       const float* __restrict__ be1,
                       const float* __restrict__ We2,
                       const float* __restrict__ be2,
                       const float* __restrict__ Wc1,
                       const float* __restrict__ bc1,
                       const float* __restrict__ Wc2,
                       const float* __restrict__ bc2,
                       const float* __restrict__ Wv,
                       const float* __restrict__ bv,
                       int l)
{
    __shared__ float4 sUVp[8];        // {u2c,u2c1,v2c,v2c1} x0.5
    __shared__ float4 sWCp[8];        // {w2c,w2c1,(c+be1)2c,(c+be1)2c1} x0.5
    __shared__ float2 sbe2p[8];       // {0.5be2[2c],0.5be2[2c+1]}
    __shared__ float  sWe2raw[256];   // 0.5*We2 [k*16+n]
    __shared__ float  sWc1raw[1024];  // 0.5*Wc1 [k*64+n]
    __shared__ float2 sbc1p[32];      // {0.5bc1[2c],0.5bc1[2c+1]}
    __shared__ float  sWc2s[64];      // Wc2 raw (f32)
    __shared__ float2 scj2[NN];
    __shared__ float  stj[NN];
    __shared__ uint32_t s_x1[4 * NN * XS];   // per-warp x1 tiles, f16x2 [edge][k-pair]

    const int tid   = threadIdx.x;
    const int wid   = tid >> 5;
    const int ln    = tid & 31;
    const int bb    = blockIdx.x >> 5;
    const int ibase = (blockIdx.x & 31) * 4;
    const int i     = ibase + wid;

    // ---- staging ----
    const float* we1 = We1 + l * 128;
    if (tid < 8) {
        int c0 = 2 * tid, c1 = 2 * tid + 1;
        float u0 = 0.5f * (we1[c0] + we1[16 + c0] + we1[32 + c0]);
        float u1 = 0.5f * (we1[c1] + we1[16 + c1] + we1[32 + c1]);
        float v0 = 0.5f * (we1[48 + c0] + we1[64 + c0] + we1[80 + c0]);
        float v1 = 0.5f * (we1[48 + c1] + we1[64 + c1] + we1[80 + c1]);
        float w0 = 0.5f * we1[96 + c0];
        float w1 = 0.5f * we1[96 + c1];
        float k0 = 0.5f * (we1[112 + c0] + be1[l * 16 + c0]);
        float k1 = 0.5f * (we1[112 + c1] + be1[l * 16 + c1]);
        sUVp[tid] = make_float4(u0, u1, v0, v1);
        sWCp[tid] = make_float4(w0, w1, k0, k1);
        sbe2p[tid] = make_float2(0.5f * be2[l * 16 + c0], 0.5f * be2[l * 16 + c1]);
    } else if (tid < 40) {
        int k = tid - 8;
        sbc1p[k] = make_float2(0.5f * bc1[l * 64 + 2 * k], 0.5f * bc1[l * 64 + 2 * k + 1]);
    } else if (tid < 104) {
        sWc2s[tid - 40] = Wc2[l * 64 + tid - 40];
    }
    #pragma unroll
    for (int idx = tid; idx < 256; idx += 128)
        sWe2raw[idx] = 0.5f * We2[l * 256 + idx];
    #pragma unroll
    for (int idx = tid; idx < 1024; idx += 128)
        sWc1raw[idx] = 0.5f * Wc1[l * 1024 + idx];
    {
        const float2* c2 = (const float2*)(cin + bb * NN * 2);
        scj2[tid] = c2[tid];
        stj[tid]  = t[bb * NN + tid];
    }
    __syncthreads();

    const float ti  = stj[i];
    const float2 ci = scj2[i];
    const float2 ti2 = make_float2(ti, ti);

    // ---- persistent B fragments ----
    const int p = ln & 3;
    const int g = ln >> 2;
    uint32_t b2f0[2], b2f1[2];               // We2 (0.5x)
    #pragma unroll
    for (int nt = 0; nt < 2; ++nt) {
        int col = nt * 8 + g;
        b2f0[nt] = pack_h2s(sWe2raw[(2 * p) * 16 + col],     sWe2raw[(2 * p + 1) * 16 + col]);
        b2f1[nt] = pack_h2s(sWe2raw[(2 * p + 8) * 16 + col], sWe2raw[(2 * p + 9) * 16 + col]);
    }
    uint32_t bf0[8], bf1[8];                 // Wc1 (0.5x)
    #pragma unroll
    for (int nt = 0; nt < 8; ++nt) {
        int col = nt * 8 + g;
        bf0[nt] = pack_h2s(sWc1raw[(2 * p) * 64 + col],     sWc1raw[(2 * p + 1) * 64 + col]);
        bf1[nt] = pack_h2s(sWc1raw[(2 * p + 8) * 64 + col], sWc1raw[(2 * p + 9) * 64 + col]);
    }
    // Wc2 dot B-fragments, split precision:
    //   column 0 (g==0 lanes) = f16(Wc2), column 1 (g==1 lanes) = f16 residual,
    //   columns 2..7 = 0.  w = d0 + d1 reconstructs f32-accurate dot.
    uint32_t bd0[4], bd1[4];
    #pragma unroll
    for (int c = 0; c < 4; ++c) {
        if (g == 0) {
            bd0[c] = pack_h2s(sWc2s[16 * c + 2 * p],     sWc2s[16 * c + 2 * p + 1]);
            bd1[c] = pack_h2s(sWc2s[16 * c + 2 * p + 8], sWc2s[16 * c + 2 * p + 9]);
        } else if (g == 1) {
            bd0[c] = pack_h2s(h16res(sWc2s[16 * c + 2 * p]),
                              h16res(sWc2s[16 * c + 2 * p + 1]));
            bd1[c] = pack_h2s(h16res(sWc2s[16 * c + 2 * p + 8]),
                              h16res(sWc2s[16 * c + 2 * p + 9]));
        } else {
            bd0[c] = 0u;
            bd1[c] = 0u;
        }
    }
    const float2 be2b0 = sbe2p[p];
    const float2 be2b1 = sbe2p[p + 4];

    // ---- phase 1: x1 (f32 matvec, f16x2 silu) -> f16 edge-major shared ----
    uint32_t* sx = s_x1 + wid * NN * XS;
    #pragma unroll
    for (int ee = 0; ee < 4; ++ee) {
        const int e = ln + 32 * ee;
        const float tj = stj[e];
        const float2 cj = scj2[e];
        const float dx = ci.x - cj.x;
        const float dy = ci.y - cj.y;
        const float d = fmaf(dx, dx, dy * dy);
        const float2 tj2 = make_float2(tj, tj);
        const float2 d2  = make_float2(d, d);
        #pragma unroll
        for (int cp = 0; cp < 8; ++cp) {
            float4 uv = sUVp[cp];
            float4 wc = sWCp[cp];
            float2 h = ffma2(ti2, make_float2(uv.x, uv.y),
                      ffma2(tj2, make_float2(uv.z, uv.w),
                      ffma2(d2,  make_float2(wc.x, wc.y),
                                 make_float2(wc.z, wc.w))));
            sx[e * XS + cp] = silu_h2_pre(f2_to_h2(h));
        }
    }
    __syncwarp();

    // ---- phase 2: 8 tiles of 16 edges ----
    const float bc2c = (p == 0) ? bc2[l] : 0.0f;   // bc2 enters dot-mma C, col 0 only
    float ax = 0.0f, ay = 0.0f;

    #pragma unroll
    for (int r = 0; r < 8; ++r) {
        const int elo = 16 * r + g;
        const int ehi = elo + 8;
        uint32_t a0 = sx[elo * XS + p];
        uint32_t a1 = sx[ehi * XS + p];
        uint32_t a2 = sx[elo * XS + p + 4];
        uint32_t a3 = sx[ehi * XS + p + 4];

        // MLP2: q = silu(silu(x1 @ We2 + be2)); f16x2 silu chain into MLP3 A frags
        uint32_t qa0, qa1, qa2, qa3;
        {
            float d0, d1, d2, d3;
            mma16816c(d0, d1, d2, d3, a0, a1, a2, a3, b2f0[0], b2f1[0],
                      be2b0.x, be2b0.y, be2b0.x, be2b0.y);
            qa0 = silu_h2(silu_h2_pre(f2_to_h2(make_float2(d0, d1))));
            qa1 = silu_h2(silu_h2_pre(f2_to_h2(make_float2(d2, d3))));
            mma16816c(d0, d1, d2, d3, a0, a1, a2, a3, b2f0[1], b2f1[1],
                      be2b1.x, be2b1.y, be2b1.x, be2b1.y);
            qa2 = silu_h2(silu_h2_pre(f2_to_h2(make_float2(d0, d1))));
            qa3 = silu_h2(silu_h2_pre(f2_to_h2(make_float2(d2, d3))));
        }

        // MLP3 + dot: 4 K-chunks; h stays f16, w = h @ Wc2 + bc2 on tensor pipe
        float w0 = bc2c, w1 = 0.0f, w2 = bc2c, w3 = 0.0f;
        #pragma unroll
        for (int c = 0; c < 4; ++c) {
            float d0, d1, d2, d3;
            float2 bw = sbc1p[4 * (2 * c) + p];
            mma16816c(d0, d1, d2, d3, qa0, qa1, qa2, qa3, bf0[2 * c], bf1[2 * c],
                      bw.x, bw.y, bw.x, bw.y);
            uint32_t ha0 = silu_h2_pre(f2_to_h2(make_float2(d0, d1)));
            uint32_t ha1 = silu_h2_pre(f2_to_h2(make_float2(d2, d3)));
            bw = sbc1p[4 * (2 * c + 1) + p];
            mma16816c(d0, d1, d2, d3, qa0, qa1, qa2, qa3, bf0[2 * c + 1], bf1[2 * c + 1],
                      bw.x, bw.y, bw.x, bw.y);
            uint32_t ha2 = silu_h2_pre(f2_to_h2(make_float2(d0, d1)));
            uint32_t ha3 = silu_h2_pre(f2_to_h2(make_float2(d2, d3)));
            mma16816c(w0, w1, w2, w3, ha0, ha1, ha2, ha3, bd0[c], bd1[c],
                      w0, w1, w2, w3);
        }
        // hi+lo reconstruction: w_ij(elo) = w0+w1, w_ij(ehi) = w2+w3 (p==0 lanes)
        float wE  = w0 + w1;
        float wE8 = w2 + w3;
        float2 cjE  = scj2[elo];
        float2 cjE8 = scj2[ehi];
        ax += wE * (ci.x - cjE.x) + wE8 * (ci.x - cjE8.x);
        ay += wE * (ci.y - cjE.y) + wE8 * (ci.y - cjE8.y);
    }

    // ---- warp reduce + node update ----
    #pragma unroll
    for (int off = 16; off > 0; off >>= 1) {
        ax += __shfl_down_sync(0xFFFFFFFFu, ax, off);
        ay += __shfl_down_sync(0xFFFFFFFFu, ay, off);
    }
    if (ln == 0) {
        float wv  = Wv[l * 3] + Wv[l * 3 + 1] + Wv[l * 3 + 2];
        float phi = fmaf(ti, wv, bv[l]);
        float vx = vin[(bb * NN + i) * 2];
        float vy = vin[(bb * NN + i) * 2 + 1];
        float nvx = fmaf(phi, vx, ax);
        float nvy = fmaf(phi, vy, ay);
        float ncx = ci.x + nvx;
        float ncy = ci.y + nvy;
        cout[(bb * NN + i) * 2]     = seluf(ncx);
        cout[(bb * NN + i) * 2 + 1] = seluf(ncy);
        vout[(bb * NN + i) * 2]     = seluf(nvx);
        vout[(bb * NN + i) * 2 + 1] = seluf(nvy);
    }
}

__global__ void egnn_head_kernel(const float* __restrict__ cin,
                                 const float* __restrict__ vin,
                                 const float* __restrict__ Wconv1,
                                 const float* __restrict__ bconv1,
                                 const float* __restrict__ Wconv2,
                                 const float* __restrict__ bconv2,
                                 float* __restrict__ out)
{
    int idx = blockIdx.x * blockDim.x + threadIdx.x;
    if (idx >= BB * NN) return;

    float x0 = seluf(cin[idx * 2]);
    float x1 = seluf(cin[idx * 2 + 1]);
    float x2 = seluf(vin[idx * 2]);
    float x3 = seluf(vin[idx * 2 + 1]);

    float y0 = bconv2[0], y1 = bconv2[1], y2 = bconv2[2], y3 = bconv2[3];
    #pragma unroll
    for (int o = 0; o < 32; o++) {
        float h = bconv1[o];
        h = fmaf(x0, Wconv1[o * 4 + 0], h);
        h = fmaf(x1, Wconv1[o * 4 + 1], h);
        h = fmaf(x2, Wconv1[o * 4 + 2], h);
        h = fmaf(x3, Wconv1[o * 4 + 3], h);
        h = seluf(h);
        y0 = fmaf(h, Wconv2[0 * 32 + o], y0);
        y1 = fmaf(h, Wconv2[1 * 32 + o], y1);
        y2 = fmaf(h, Wconv2[2 * 32 + o], y2);
        y3 = fmaf(h, Wconv2[3 * 32 + o], y3);
    }
    out[idx * 2]                   = y0;
    out[idx * 2 + 1]               = y1;
    out[BB * NN * 2 + idx * 2]     = y2;
    out[BB * NN * 2 + idx * 2 + 1] = y3;
}

extern "C" void kernel_launch(void* const* d_in, const int* in_sizes, int n_in,
                              void* d_out, int out_size)
{
    const float* t      = (const float*)d_in[0];
    const float* coors  = (const float*)d_in[1];
    const float* vel    = (const float*)d_in[2];
    const float* We1    = (const float*)d_in[3];
    const float* be1    = (const float*)d_in[4];
    const float* We2    = (const float*)d_in[5];
    const float* be2    = (const float*)d_in[6];
    const float* Wc1    = (const float*)d_in[7];
    const float* bc1    = (const float*)d_in[8];
    const float* Wc2    = (const float*)d_in[9];
    const float* bc2    = (const float*)d_in[10];
    const float* Wv     = (const float*)d_in[11];
    const float* bv     = (const float*)d_in[12];
    const float* Wconv1 = (const float*)d_in[13];
    const float* bconv1 = (const float*)d_in[14];
    const float* Wconv2 = (const float*)d_in[15];
    const float* bconv2 = (const float*)d_in[16];
    float* out = (float*)d_out;

    float *c0, *v0, *c1, *v1;
    cudaGetSymbolAddress((void**)&c0, g_c0);
    cudaGetSymbolAddress((void**)&v0, g_v0);
    cudaGetSymbolAddress((void**)&c1, g_c1);
    cudaGetSymbolAddress((void**)&v1, g_v1);

    dim3 grid(BB * 32);   // 2048 blocks: (batch, group of 4 i's), warp-per-i
    dim3 blk(128);
    egnn_layer_kernel<<<grid, blk>>>(t, coors, vel, c0, v0,
                                     We1, be1, We2, be2, Wc1, bc1, Wc2, bc2,
                                     Wv, bv, 0);
    egnn_layer_kernel<<<grid, blk>>>(t, c0, v0, c1, v1,
                                     We1, be1, We2, be2, Wc1, bc1, Wc2, bc2,
                                     Wv, bv, 1);
    egnn_head_kernel<<<(BB * NN + 127) / 128, 128>>>(c1, v1, Wconv1, bconv1,
                                                     Wconv2, bconv2, out);
}

// round 13
// speedup vs baseline: 1.0997x; 1.0739x over previous
#include <cuda_runtime.h>
#include <cuda_fp16.h>
#include <math.h>
#include <cstdint>

#define BB 64
#define NN 128
#define XS 9   // words per edge row in s_x1 (stride padding)

// scratch for intermediate coors/vel between layers (no allocs allowed)
__device__ float g_c0[BB*NN*2];
__device__ float g_v0[BB*NN*2];
__device__ float g_c1[BB*NN*2];
__device__ float g_v1[BB*NN*2];

union F2U { float2 f; unsigned long long u; };
union H2U { __half2 h; uint32_t u; };

__device__ __forceinline__ float2 ffma2(float2 a, float2 b, float2 c) {
    F2U A, B, C, R;
    A.f = a; B.f = b; C.f = c;
    asm("fma.rn.f32x2 %0, %1, %2, %3;" : "=l"(R.u) : "l"(A.u), "l"(B.u), "l"(C.u));
    return R.f;
}

// ---- packed f16x2 silu machinery ----
__device__ __forceinline__ uint32_t f2_to_h2(float2 v) {
    uint32_t r;  // d.hi = first src, d.lo = second src
    asm("cvt.rn.f16x2.f32 %0, %1, %2;" : "=r"(r) : "f"(v.y), "f"(v.x));
    return r;
}
__device__ __forceinline__ uint32_t tanh_h2(uint32_t x) {
    uint32_t r;
    asm("tanh.approx.f16x2 %0, %1;" : "=r"(r) : "r"(x));
    return r;
}
__device__ __forceinline__ uint32_t hfma2u(uint32_t a, uint32_t b, uint32_t c) {
    H2U A, B, C, R;
    A.u = a; B.u = b; C.u = c;
    R.h = __hfma2(A.h, B.h, C.h);
    return R.u;
}
__device__ __forceinline__ uint32_t hmul2u(uint32_t a, uint32_t b) {
    H2U A, B, R;
    A.u = a; B.u = b;
    R.h = __hmul2(A.h, B.h);
    return R.u;
}
// h = x/2 packed f16x2 -> silu(x) = h + h*tanh(h), all f16x2
__device__ __forceinline__ uint32_t silu_h2_pre(uint32_t h) {
    return hfma2u(h, tanh_h2(h), h);
}
// full silu on packed x
__device__ __forceinline__ uint32_t silu_h2(uint32_t x) {
    H2U half_c; half_c.h = __floats2half2_rn(0.5f, 0.5f);
    return silu_h2_pre(hmul2u(x, half_c.u));
}

__device__ __forceinline__ float seluf(float x) {
    const float scale = 1.0507009873554805f;
    const float alpha = 1.6732632423543772f;
    return x > 0.0f ? scale * x : scale * alpha * expm1f(x);
}

__device__ __forceinline__ uint32_t pack_h2s(float a, float b) {
    H2U c; c.h = __floats2half2_rn(a, b);
    return c.u;
}
// residual after f16 rounding
__device__ __forceinline__ float h16res(float v) {
    return v - __half2float(__float2half_rn(v));
}

// mma.m16n8k16, f32 C/D (used for the final Wc2 dot only)
__device__ __forceinline__ void mma16816c(float& d0, float& d1, float& d2, float& d3,
                                          uint32_t a0, uint32_t a1, uint32_t a2, uint32_t a3,
                                          uint32_t b0, uint32_t b1,
                                          float c0, float c1, float c2, float c3) {
    asm("mma.sync.aligned.m16n8k16.row.col.f32.f16.f16.f32 "
        "{%0,%1,%2,%3}, {%4,%5,%6,%7}, {%8,%9}, {%10,%11,%12,%13};"
        : "=f"(d0), "=f"(d1), "=f"(d2), "=f"(d3)
        : "r"(a0), "r"(a1), "r"(a2), "r"(a3), "r"(b0), "r"(b1),
          "f"(c0), "f"(c1), "f"(c2), "f"(c3));
}

// mma.m16n8k16, f16 C/D: D comes back as 2 packed f16x2 regs matching the
// silu operand and downstream A-fragment layout exactly (no cvt needed).
__device__ __forceinline__ void mma16816h(uint32_t& d0, uint32_t& d1,
                                          uint32_t a0, uint32_t a1, uint32_t a2, uint32_t a3,
                                          uint32_t b0, uint32_t b1,
                                          uint32_t c0, uint32_t c1) {
    asm("mma.sync.aligned.m16n8k16.row.col.f16.f16.f16.f16 "
        "{%0,%1}, {%2,%3,%4,%5}, {%6,%7}, {%8,%9};"
        : "=r"(d0), "=r"(d1)
        : "r"(a0), "r"(a1), "r"(a2), "r"(a3), "r"(b0), "r"(b1),
          "r"(c0), "r"(c1));
}

__global__ __launch_bounds__(128, 5)
void egnn_layer_kernel(const float* __restrict__ t,
                       const float* __restrict__ cin,
                       const float* __restrict__ vin,
                       float* __restrict__ cout,
                       float* __restrict__ vout,
                       const float* __restrict__ We1,
                       const float* __restrict__ be1,
                       const float* __restrict__ We2,
                       const float* __restrict__ be2,
                       const float* __restrict__ Wc1,
                       const float* __restrict__ bc1,
                       const float* __restrict__ Wc2,
                       const float* __restrict__ bc2,
                       const float* __restrict__ Wv,
                       const float* __restrict__ bv,
                       int l)
{
    __shared__ float4 sUVp[8];          // {u2c,u2c1,v2c,v2c1} x0.5
    __shared__ float4 sWCp[8];          // {w2c,w2c1,(c+be1)2c,(c+be1)2c1} x0.5
    __shared__ uint32_t sbe2h[8];       // f16x2 {0.5be2[2c],0.5be2[2c+1]}
    __shared__ float  sWe2raw[256];     // 0.5*We2 [k*16+n]
    __shared__ float  sWc1raw[1024];    // 0.5*Wc1 [k*64+n]
    __shared__ uint32_t sbc1h[32];      // f16x2 {0.5bc1[2c],0.5bc1[2c+1]}
    __shared__ float  sWc2s[64];        // Wc2 raw (f32)
    __shared__ float2 scj2[NN];
    __shared__ float  stj[NN];
    __shared__ uint32_t s_x1[4 * NN * XS];   // per-warp x1 tiles, f16x2 [edge][k-pair]

    const int tid   = threadIdx.x;
    const int wid   = tid >> 5;
    const int ln    = tid & 31;
    const int bb    = blockIdx.x >> 5;
    const int ibase = (blockIdx.x & 31) * 4;
    const int i     = ibase + wid;

    // ---- staging ----
    const float* we1 = We1 + l * 128;
    if (tid < 8) {
        int c0 = 2 * tid, c1 = 2 * tid + 1;
        float u0 = 0.5f * (we1[c0] + we1[16 + c0] + we1[32 + c0]);
        float u1 = 0.5f * (we1[c1] + we1[16 + c1] + we1[32 + c1]);
        float v0 = 0.5f * (we1[48 + c0] + we1[64 + c0] + we1[80 + c0]);
        float v1 = 0.5f * (we1[48 + c1] + we1[64 + c1] + we1[80 + c1]);
        float w0 = 0.5f * we1[96 + c0];
        float w1 = 0.5f * we1[96 + c1];
        float k0 = 0.5f * (we1[112 + c0] + be1[l * 16 + c0]);
        float k1 = 0.5f * (we1[112 + c1] + be1[l * 16 + c1]);
        sUVp[tid] = make_float4(u0, u1, v0, v1);
        sWCp[tid] = make_float4(w0, w1, k0, k1);
        sbe2h[tid] = pack_h2s(0.5f * be2[l * 16 + c0], 0.5f * be2[l * 16 + c1]);
    } else if (tid < 40) {
        int k = tid - 8;
        sbc1h[k] = pack_h2s(0.5f * bc1[l * 64 + 2 * k], 0.5f * bc1[l * 64 + 2 * k + 1]);
    } else if (tid < 104) {
        sWc2s[tid - 40] = Wc2[l * 64 + tid - 40];
    }
    #pragma unroll
    for (int idx = tid; idx < 256; idx += 128)
        sWe2raw[idx] = 0.5f * We2[l * 256 + idx];
    #pragma unroll
    for (int idx = tid; idx < 1024; idx += 128)
        sWc1raw[idx] = 0.5f * Wc1[l * 1024 + idx];
    {
        const float2* c2 = (const float2*)(cin + bb * NN * 2);
        scj2[tid] = c2[tid];
        stj[tid]  = t[bb * NN + tid];
    }
    __syncthreads();

    const float ti  = stj[i];
    const float2 ci = scj2[i];
    const float2 ti2 = make_float2(ti, ti);

    // ---- persistent B fragments ----
    const int p = ln & 3;
    const int g = ln >> 2;
    uint32_t b2f0[2], b2f1[2];               // We2 (0.5x)
    #pragma unroll
    for (int nt = 0; nt < 2; ++nt) {
        int col = nt * 8 + g;
        b2f0[nt] = pack_h2s(sWe2raw[(2 * p) * 16 + col],     sWe2raw[(2 * p + 1) * 16 + col]);
        b2f1[nt] = pack_h2s(sWe2raw[(2 * p + 8) * 16 + col], sWe2raw[(2 * p + 9) * 16 + col]);
    }
    uint32_t bf0[8], bf1[8];                 // Wc1 (0.5x)
    #pragma unroll
    for (int nt = 0; nt < 8; ++nt) {
        int col = nt * 8 + g;
        bf0[nt] = pack_h2s(sWc1raw[(2 * p) * 64 + col],     sWc1raw[(2 * p + 1) * 64 + col]);
        bf1[nt] = pack_h2s(sWc1raw[(2 * p + 8) * 64 + col], sWc1raw[(2 * p + 9) * 64 + col]);
    }
    // Wc2 dot B-fragments, split precision (col0 = f16(Wc2), col1 = residual)
    uint32_t bd0[4], bd1[4];
    #pragma unroll
    for (int c = 0; c < 4; ++c) {
        if (g == 0) {
            bd0[c] = pack_h2s(sWc2s[16 * c + 2 * p],     sWc2s[16 * c + 2 * p + 1]);
            bd1[c] = pack_h2s(sWc2s[16 * c + 2 * p + 8], sWc2s[16 * c + 2 * p + 9]);
        } else if (g == 1) {
            bd0[c] = pack_h2s(h16res(sWc2s[16 * c + 2 * p]),
                              h16res(sWc2s[16 * c + 2 * p + 1]));
            bd1[c] = pack_h2s(h16res(sWc2s[16 * c + 2 * p + 8]),
                              h16res(sWc2s[16 * c + 2 * p + 9]));
        } else {
            bd0[c] = 0u;
            bd1[c] = 0u;
        }
    }
    const uint32_t be2h0 = sbe2h[p];
    const uint32_t be2h1 = sbe2h[p + 4];

    // ---- phase 1: x1 (f32 matvec, f16x2 silu) -> f16 edge-major shared ----
    uint32_t* sx = s_x1 + wid * NN * XS;
    #pragma unroll
    for (int ee = 0; ee < 4; ++ee) {
        const int e = ln + 32 * ee;
        const float tj = stj[e];
        const float2 cj = scj2[e];
        const float dx = ci.x - cj.x;
        const float dy = ci.y - cj.y;
        const float d = fmaf(dx, dx, dy * dy);
        const float2 tj2 = make_float2(tj, tj);
        const float2 d2  = make_float2(d, d);
        #pragma unroll
        for (int cp = 0; cp < 8; ++cp) {
            float4 uv = sUVp[cp];
            float4 wc = sWCp[cp];
            float2 h = ffma2(ti2, make_float2(uv.x, uv.y),
                      ffma2(tj2, make_float2(uv.z, uv.w),
                      ffma2(d2,  make_float2(wc.x, wc.y),
                                 make_float2(wc.z, wc.w))));
            sx[e * XS + cp] = silu_h2_pre(f2_to_h2(h));
        }
    }
    __syncwarp();

    // ---- phase 2: 8 tiles of 16 edges, all-f16 mma chains ----
    const float bc2c = (p == 0) ? bc2[l] : 0.0f;   // bc2 enters dot-mma C, col 0 only
    float ax = 0.0f, ay = 0.0f;

    #pragma unroll
    for (int r = 0; r < 8; ++r) {
        const int elo = 16 * r + g;
        const int ehi = elo + 8;
        uint32_t a0 = sx[elo * XS + p];
        uint32_t a1 = sx[ehi * XS + p];
        uint32_t a2 = sx[elo * XS + p + 4];
        uint32_t a3 = sx[ehi * XS + p + 4];

        // MLP2: q = silu(silu(x1 @ We2 + be2)); f16-out D chains straight to silu
        uint32_t qa0, qa1, qa2, qa3;
        {
            uint32_t D0, D1;
            mma16816h(D0, D1, a0, a1, a2, a3, b2f0[0], b2f1[0], be2h0, be2h0);
            qa0 = silu_h2(silu_h2_pre(D0));
            qa1 = silu_h2(silu_h2_pre(D1));
            mma16816h(D0, D1, a0, a1, a2, a3, b2f0[1], b2f1[1], be2h1, be2h1);
            qa2 = silu_h2(silu_h2_pre(D0));
            qa3 = silu_h2(silu_h2_pre(D1));
        }

        // MLP3 + dot: 4 K-chunks; f16-out h mmas, f32-out dot mma
        float w0 = bc2c, w1 = 0.0f, w2 = bc2c, w3 = 0.0f;
        #pragma unroll
        for (int c = 0; c < 4; ++c) {
            uint32_t D0, D1, E0, E1;
            uint32_t bb0 = sbc1h[4 * (2 * c) + p];
            mma16816h(D0, D1, qa0, qa1, qa2, qa3, bf0[2 * c], bf1[2 * c], bb0, bb0);
            uint32_t ha0 = silu_h2_pre(D0);
            uint32_t ha1 = silu_h2_pre(D1);
            uint32_t bb1 = sbc1h[4 * (2 * c + 1) + p];
            mma16816h(E0, E1, qa0, qa1, qa2, qa3, bf0[2 * c + 1], bf1[2 * c + 1], bb1, bb1);
            uint32_t ha2 = silu_h2_pre(E0);
            uint32_t ha3 = silu_h2_pre(E1);
            mma16816c(w0, w1, w2, w3, ha0, ha1, ha2, ha3, bd0[c], bd1[c],
                      w0, w1, w2, w3);
        }
        // hi+lo reconstruction: w_ij(elo) = w0+w1, w_ij(ehi) = w2+w3 (p==0 lanes)
        float wE  = w0 + w1;
        float wE8 = w2 + w3;
        float2 cjE  = scj2[elo];
        float2 cjE8 = scj2[ehi];
        ax += wE * (ci.x - cjE.x) + wE8 * (ci.x - cjE8.x);
        ay += wE * (ci.y - cjE.y) + wE8 * (ci.y - cjE8.y);
    }

    // ---- warp reduce + node update ----
    #pragma unroll
    for (int off = 16; off > 0; off >>= 1) {
        ax += __shfl_down_sync(0xFFFFFFFFu, ax, off);
        ay += __shfl_down_sync(0xFFFFFFFFu, ay, off);
    }
    if (ln == 0) {
        float wv  = Wv[l * 3] + Wv[l * 3 + 1] + Wv[l * 3 + 2];
        float phi = fmaf(ti, wv, bv[l]);
        float vx = vin[(bb * NN + i) * 2];
        float vy = vin[(bb * NN + i) * 2 + 1];
        float nvx = fmaf(phi, vx, ax);
        float nvy = fmaf(phi, vy, ay);
        float ncx = ci.x + nvx;
        float ncy = ci.y + nvy;
        cout[(bb * NN + i) * 2]     = seluf(ncx);
        cout[(bb * NN + i) * 2 + 1] = seluf(ncy);
        vout[(bb * NN + i) * 2]     = seluf(nvx);
        vout[(bb * NN + i) * 2 + 1] = seluf(nvy);
    }
}

__global__ void egnn_head_kernel(const float* __restrict__ cin,
                                 const float* __restrict__ vin,
                                 const float* __restrict__ Wconv1,
                                 const float* __restrict__ bconv1,
                                 const float* __restrict__ Wconv2,
                                 const float* __restrict__ bconv2,
                                 float* __restrict__ out)
{
    int idx = blockIdx.x * blockDim.x + threadIdx.x;
    if (idx >= BB * NN) return;

    float x0 = seluf(cin[idx * 2]);
    float x1 = seluf(cin[idx * 2 + 1]);
    float x2 = seluf(vin[idx * 2]);
    float x3 = seluf(vin[idx * 2 + 1]);

    float y0 = bconv2[0], y1 = bconv2[1], y2 = bconv2[2], y3 = bconv2[3];
    #pragma unroll
    for (int o = 0; o < 32; o++) {
        float h = bconv1[o];
        h = fmaf(x0, Wconv1[o * 4 + 0], h);
        h = fmaf(x1, Wconv1[o * 4 + 1], h);
        h = fmaf(x2, Wconv1[o * 4 + 2], h);
        h = fmaf(x3, Wconv1[o * 4 + 3], h);
        h = seluf(h);
        y0 = fmaf(h, Wconv2[0 * 32 + o], y0);
        y1 = fmaf(h, Wconv2[1 * 32 + o], y1);
        y2 = fmaf(h, Wconv2[2 * 32 + o], y2);
        y3 = fmaf(h, Wconv2[3 * 32 + o], y3);
    }
    out[idx * 2]                   = y0;
    out[idx * 2 + 1]               = y1;
    out[BB * NN * 2 + idx * 2]     = y2;
    out[BB * NN * 2 + idx * 2 + 1] = y3;
}

extern "C" void kernel_launch(void* const* d_in, const int* in_sizes, int n_in,
                              void* d_out, int out_size)
{
    const float* t      = (const float*)d_in[0];
    const float* coors  = (const float*)d_in[1];
    const float* vel    = (const float*)d_in[2];
    const float* We1    = (const float*)d_in[3];
    const float* be1    = (const float*)d_in[4];
    const float* We2    = (const float*)d_in[5];
    const float* be2    = (const float*)d_in[6];
    const float* Wc1    = (const float*)d_in[7];
    const float* bc1    = (const float*)d_in[8];
    const float* Wc2    = (const float*)d_in[9];
    const float* bc2    = (const float*)d_in[10];
    const float* Wv     = (const float*)d_in[11];
    const float* bv     = (const float*)d_in[12];
    const float* Wconv1 = (const float*)d_in[13];
    const float* bconv1 = (const float*)d_in[14];
    const float* Wconv2 = (const float*)d_in[15];
    const float* bconv2 = (const float*)d_in[16];
    float* out = (float*)d_out;

    float *c0, *v0, *c1, *v1;
    cudaGetSymbolAddress((void**)&c0, g_c0);
    cudaGetSymbolAddress((void**)&v0, g_v0);
    cudaGetSymbolAddress((void**)&c1, g_c1);
    cudaGetSymbolAddress((void**)&v1, g_v1);

    dim3 grid(BB * 32);   // 2048 blocks: (batch, group of 4 i's), warp-per-i
    dim3 blk(128);
    egnn_layer_kernel<<<grid, blk>>>(t, coors, vel, c0, v0,
                                     We1, be1, We2, be2, Wc1, bc1, Wc2, bc2,
                                     Wv, bv, 0);
    egnn_layer_kernel<<<grid, blk>>>(t, c0, v0, c1, v1,
                                     We1, be1, We2, be2, Wc1, bc1, Wc2, bc2,
                                     Wv, bv, 1);
    egnn_head_kernel<<<(BB * NN + 127) / 128, 128>>>(c1, v1, Wconv1, bconv1,
                                                     Wconv2, bconv2, out);
}

// round 14
// speedup vs baseline: 1.1275x; 1.0253x over previous
#include <cuda_runtime.h>
#include <cuda_fp16.h>
#include <math.h>
#include <cstdint>

#define BB 64
#define NN 128
#define XS 9   // words per edge row in s_x1 (stride padding)

// scratch for intermediate coors/vel between layers (no allocs allowed)
__device__ float g_c0[BB*NN*2];
__device__ float g_v0[BB*NN*2];
__device__ float g_c1[BB*NN*2];
__device__ float g_v1[BB*NN*2];

union F2U { float2 f; unsigned long long u; };
union H2U { __half2 h; uint32_t u; };

__device__ __forceinline__ float2 ffma2(float2 a, float2 b, float2 c) {
    F2U A, B, C, R;
    A.f = a; B.f = b; C.f = c;
    asm("fma.rn.f32x2 %0, %1, %2, %3;" : "=l"(R.u) : "l"(A.u), "l"(B.u), "l"(C.u));
    return R.f;
}

// ---- packed f16x2 silu machinery ----
__device__ __forceinline__ uint32_t f2_to_h2(float2 v) {
    uint32_t r;  // d.hi = first src, d.lo = second src
    asm("cvt.rn.f16x2.f32 %0, %1, %2;" : "=r"(r) : "f"(v.y), "f"(v.x));
    return r;
}
__device__ __forceinline__ uint32_t tanh_h2(uint32_t x) {
    uint32_t r;
    asm("tanh.approx.f16x2 %0, %1;" : "=r"(r) : "r"(x));
    return r;
}
__device__ __forceinline__ uint32_t hfma2u(uint32_t a, uint32_t b, uint32_t c) {
    H2U A, B, C, R;
    A.u = a; B.u = b; C.u = c;
    R.h = __hfma2(A.h, B.h, C.h);
    return R.u;
}
__device__ __forceinline__ uint32_t hmul2u(uint32_t a, uint32_t b) {
    H2U A, B, R;
    A.u = a; B.u = b;
    R.h = __hmul2(A.h, B.h);
    return R.u;
}
// h = x/2 packed f16x2 -> silu(x) = h + h*tanh(h), all f16x2
__device__ __forceinline__ uint32_t silu_h2_pre(uint32_t h) {
    return hfma2u(h, tanh_h2(h), h);
}
// full silu on packed x
__device__ __forceinline__ uint32_t silu_h2(uint32_t x) {
    H2U half_c; half_c.h = __floats2half2_rn(0.5f, 0.5f);
    return silu_h2_pre(hmul2u(x, half_c.u));
}

__device__ __forceinline__ float seluf(float x) {
    const float scale = 1.0507009873554805f;
    const float alpha = 1.6732632423543772f;
    return x > 0.0f ? scale * x : scale * alpha * expm1f(x);
}

__device__ __forceinline__ uint32_t pack_h2s(float a, float b) {
    H2U c; c.h = __floats2half2_rn(a, b);
    return c.u;
}
// residual after f16 rounding
__device__ __forceinline__ float h16res(float v) {
    return v - __half2float(__float2half_rn(v));
}

// mma.m16n8k16, f32 C/D (used for the final Wc2 dot only)
__device__ __forceinline__ void mma16816c(float& d0, float& d1, float& d2, float& d3,
                                          uint32_t a0, uint32_t a1, uint32_t a2, uint32_t a3,
                                          uint32_t b0, uint32_t b1,
                                          float c0, float c1, float c2, float c3) {
    asm("mma.sync.aligned.m16n8k16.row.col.f32.f16.f16.f32 "
        "{%0,%1,%2,%3}, {%4,%5,%6,%7}, {%8,%9}, {%10,%11,%12,%13};"
        : "=f"(d0), "=f"(d1), "=f"(d2), "=f"(d3)
        : "r"(a0), "r"(a1), "r"(a2), "r"(a3), "r"(b0), "r"(b1),
          "f"(c0), "f"(c1), "f"(c2), "f"(c3));
}

// mma.m16n8k16, f16 C/D
__device__ __forceinline__ void mma16816h(uint32_t& d0, uint32_t& d1,
                                          uint32_t a0, uint32_t a1, uint32_t a2, uint32_t a3,
                                          uint32_t b0, uint32_t b1,
                                          uint32_t c0, uint32_t c1) {
    asm("mma.sync.aligned.m16n8k16.row.col.f16.f16.f16.f16 "
        "{%0,%1}, {%2,%3,%4,%5}, {%6,%7}, {%8,%9};"
        : "=r"(d0), "=r"(d1)
        : "r"(a0), "r"(a1), "r"(a2), "r"(a3), "r"(b0), "r"(b1),
          "r"(c0), "r"(c1));
}

__global__ __launch_bounds__(128, 4)
void egnn_layer_kernel(const float* __restrict__ t,
                       const float* __restrict__ cin,
                       const float* __restrict__ vin,
                       float* __restrict__ cout,
                       float* __restrict__ vout,
                       const float* __restrict__ We1,
                       const float* __restrict__ be1,
                       const float* __restrict__ We2,
                       const float* __restrict__ be2,
                       const float* __restrict__ Wc1,
                       const float* __restrict__ bc1,
                       const float* __restrict__ Wc2,
                       const float* __restrict__ bc2,
                       const float* __restrict__ Wv,
                       const float* __restrict__ bv,
                       int l)
{
    __shared__ float4 sUVp[8];          // {u2c,u2c1,v2c,v2c1} x0.5
    __shared__ float4 sWCp[8];          // {w2c,w2c1,(c+be1)2c,(c+be1)2c1} x0.5
    __shared__ uint32_t sbe2h[8];       // f16x2 {0.5be2[2c],0.5be2[2c+1]}
    __shared__ float  sWe2raw[256];     // 0.5*We2 [k*16+n]
    __shared__ float  sWc1raw[1024];    // 0.5*Wc1 [k*64+n]
    __shared__ uint32_t sbc1h[32];      // f16x2 {0.5bc1[2c],0.5bc1[2c+1]}
    __shared__ float  sWc2s[64];        // Wc2 raw (f32)
    __shared__ float2 scj2[NN];
    __shared__ float  stj[NN];
    __shared__ uint32_t s_x1[4 * NN * XS];   // per-warp x1 tiles, f16x2 [edge][k-pair]

    const int tid   = threadIdx.x;
    const int wid   = tid >> 5;
    const int ln    = tid & 31;
    const int bb    = blockIdx.x >> 5;
    const int ibase = (blockIdx.x & 31) * 4;
    const int i     = ibase + wid;

    // ---- staging ----
    const float* we1 = We1 + l * 128;
    if (tid < 8) {
        int c0 = 2 * tid, c1 = 2 * tid + 1;
        float u0 = 0.5f * (we1[c0] + we1[16 + c0] + we1[32 + c0]);
        float u1 = 0.5f * (we1[c1] + we1[16 + c1] + we1[32 + c1]);
        float v0 = 0.5f * (we1[48 + c0] + we1[64 + c0] + we1[80 + c0]);
        float v1 = 0.5f * (we1[48 + c1] + we1[64 + c1] + we1[80 + c1]);
        float w0 = 0.5f * we1[96 + c0];
        float w1 = 0.5f * we1[96 + c1];
        float k0 = 0.5f * (we1[112 + c0] + be1[l * 16 + c0]);
        float k1 = 0.5f * (we1[112 + c1] + be1[l * 16 + c1]);
        sUVp[tid] = make_float4(u0, u1, v0, v1);
        sWCp[tid] = make_float4(w0, w1, k0, k1);
        sbe2h[tid] = pack_h2s(0.5f * be2[l * 16 + c0], 0.5f * be2[l * 16 + c1]);
    } else if (tid < 40) {
        int k = tid - 8;
        sbc1h[k] = pack_h2s(0.5f * bc1[l * 64 + 2 * k], 0.5f * bc1[l * 64 + 2 * k + 1]);
    } else if (tid < 104) {
        sWc2s[tid - 40] = Wc2[l * 64 + tid - 40];
    }
    #pragma unroll
    for (int idx = tid; idx < 256; idx += 128)
        sWe2raw[idx] = 0.5f * We2[l * 256 + idx];
    #pragma unroll
    for (int idx = tid; idx < 1024; idx += 128)
        sWc1raw[idx] = 0.5f * Wc1[l * 1024 + idx];
    {
        const float2* c2 = (const float2*)(cin + bb * NN * 2);
        scj2[tid] = c2[tid];
        stj[tid]  = t[bb * NN + tid];
    }
    __syncthreads();

    const float ti  = stj[i];
    const float2 ci = scj2[i];
    const float2 ti2 = make_float2(ti, ti);

    // ---- persistent B fragments ----
    const int p = ln & 3;
    const int g = ln >> 2;
    uint32_t b2f0[2], b2f1[2];               // We2 (0.5x)
    #pragma unroll
    for (int nt = 0; nt < 2; ++nt) {
        int col = nt * 8 + g;
        b2f0[nt] = pack_h2s(sWe2raw[(2 * p) * 16 + col],     sWe2raw[(2 * p + 1) * 16 + col]);
        b2f1[nt] = pack_h2s(sWe2raw[(2 * p + 8) * 16 + col], sWe2raw[(2 * p + 9) * 16 + col]);
    }
    uint32_t bf0[8], bf1[8];                 // Wc1 (0.5x)
    #pragma unroll
    for (int nt = 0; nt < 8; ++nt) {
        int col = nt * 8 + g;
        bf0[nt] = pack_h2s(sWc1raw[(2 * p) * 64 + col],     sWc1raw[(2 * p + 1) * 64 + col]);
        bf1[nt] = pack_h2s(sWc1raw[(2 * p + 8) * 64 + col], sWc1raw[(2 * p + 9) * 64 + col]);
    }
    // Wc2 dot B-fragments, split precision (col0 = f16(Wc2), col1 = residual)
    uint32_t bd0[4], bd1[4];
    #pragma unroll
    for (int c = 0; c < 4; ++c) {
        if (g == 0) {
            bd0[c] = pack_h2s(sWc2s[16 * c + 2 * p],     sWc2s[16 * c + 2 * p + 1]);
            bd1[c] = pack_h2s(sWc2s[16 * c + 2 * p + 8], sWc2s[16 * c + 2 * p + 9]);
        } else if (g == 1) {
            bd0[c] = pack_h2s(h16res(sWc2s[16 * c + 2 * p]),
                              h16res(sWc2s[16 * c + 2 * p + 1]));
            bd1[c] = pack_h2s(h16res(sWc2s[16 * c + 2 * p + 8]),
                              h16res(sWc2s[16 * c + 2 * p + 9]));
        } else {
            bd0[c] = 0u;
            bd1[c] = 0u;
        }
    }
    const uint32_t be2h0 = sbe2h[p];
    const uint32_t be2h1 = sbe2h[p + 4];

    // ---- phase 1: x1 (f32 matvec, f16x2 silu) -> f16 edge-major shared ----
    uint32_t* sx = s_x1 + wid * NN * XS;
    #pragma unroll
    for (int ee = 0; ee < 4; ++ee) {
        const int e = ln + 32 * ee;
        const float tj = stj[e];
        const float2 cj = scj2[e];
        const float dx = ci.x - cj.x;
        const float dy = ci.y - cj.y;
        const float d = fmaf(dx, dx, dy * dy);
        const float2 tj2 = make_float2(tj, tj);
        const float2 d2  = make_float2(d, d);
        #pragma unroll
        for (int cp = 0; cp < 8; ++cp) {
            float4 uv = sUVp[cp];
            float4 wc = sWCp[cp];
            float2 h = ffma2(ti2, make_float2(uv.x, uv.y),
                      ffma2(tj2, make_float2(uv.z, uv.w),
                      ffma2(d2,  make_float2(wc.x, wc.y),
                                 make_float2(wc.z, wc.w))));
            sx[e * XS + cp] = silu_h2_pre(f2_to_h2(h));
        }
    }
    __syncwarp();

    // ---- phase 2: 4 iterations, 2 independent 16-edge tiles each (ILP) ----
    const float bc2c = (p == 0) ? bc2[l] : 0.0f;
    float ax = 0.0f, ay = 0.0f;

    #pragma unroll
    for (int rr = 0; rr < 4; ++rr) {
        const int eloA = 16 * rr + g;
        const int ehiA = eloA + 8;
        const int eloB = eloA + 64;
        const int ehiB = eloB + 8;

        uint32_t aA0 = sx[eloA * XS + p];
        uint32_t aA1 = sx[ehiA * XS + p];
        uint32_t aA2 = sx[eloA * XS + p + 4];
        uint32_t aA3 = sx[ehiA * XS + p + 4];
        uint32_t aB0 = sx[eloB * XS + p];
        uint32_t aB1 = sx[ehiB * XS + p];
        uint32_t aB2 = sx[eloB * XS + p + 4];
        uint32_t aB3 = sx[ehiB * XS + p + 4];

        // MLP2 both tiles (4 independent mmas), then silu chains
        uint32_t qA0, qA1, qA2, qA3, qB0, qB1, qB2, qB3;
        {
            uint32_t DA0, DA1, DA2, DA3, DB0, DB1, DB2, DB3;
            mma16816h(DA0, DA1, aA0, aA1, aA2, aA3, b2f0[0], b2f1[0], be2h0, be2h0);
            mma16816h(DB0, DB1, aB0, aB1, aB2, aB3, b2f0[0], b2f1[0], be2h0, be2h0);
            mma16816h(DA2, DA3, aA0, aA1, aA2, aA3, b2f0[1], b2f1[1], be2h1, be2h1);
            mma16816h(DB2, DB3, aB0, aB1, aB2, aB3, b2f0[1], b2f1[1], be2h1, be2h1);
            qA0 = silu_h2(silu_h2_pre(DA0));
            qB0 = silu_h2(silu_h2_pre(DB0));
            qA1 = silu_h2(silu_h2_pre(DA1));
            qB1 = silu_h2(silu_h2_pre(DB1));
            qA2 = silu_h2(silu_h2_pre(DA2));
            qB2 = silu_h2(silu_h2_pre(DB2));
            qA3 = silu_h2(silu_h2_pre(DA3));
            qB3 = silu_h2(silu_h2_pre(DB3));
        }

        // MLP3 + dot, both tiles interleaved per K-chunk
        float wA0 = bc2c, wA1 = 0.0f, wA2 = bc2c, wA3 = 0.0f;
        float wB0 = bc2c, wB1 = 0.0f, wB2 = bc2c, wB3 = 0.0f;
        #pragma unroll
        for (int c = 0; c < 4; ++c) {
            uint32_t bb0 = sbc1h[4 * (2 * c) + p];
            uint32_t bb1 = sbc1h[4 * (2 * c + 1) + p];
            uint32_t DA0, DA1, EA0, EA1, DB0, DB1, EB0, EB1;
            mma16816h(DA0, DA1, qA0, qA1, qA2, qA3, bf0[2 * c], bf1[2 * c], bb0, bb0);
            mma16816h(DB0, DB1, qB0, qB1, qB2, qB3, bf0[2 * c], bf1[2 * c], bb0, bb0);
            mma16816h(EA0, EA1, qA0, qA1, qA2, qA3, bf0[2 * c + 1], bf1[2 * c + 1], bb1, bb1);
            mma16816h(EB0, EB1, qB0, qB1, qB2, qB3, bf0[2 * c + 1], bf1[2 * c + 1], bb1, bb1);
            uint32_t hA0 = silu_h2_pre(DA0);
            uint32_t hB0 = silu_h2_pre(DB0);
            uint32_t hA1 = silu_h2_pre(DA1);
            uint32_t hB1 = silu_h2_pre(DB1);
            uint32_t hA2 = silu_h2_pre(EA0);
            uint32_t hB2 = silu_h2_pre(EB0);
            uint32_t hA3 = silu_h2_pre(EA1);
            uint32_t hB3 = silu_h2_pre(EB1);
            mma16816c(wA0, wA1, wA2, wA3, hA0, hA1, hA2, hA3, bd0[c], bd1[c],
                      wA0, wA1, wA2, wA3);
            mma16816c(wB0, wB1, wB2, wB3, hB0, hB1, hB2, hB3, bd0[c], bd1[c],
                      wB0, wB1, wB2, wB3);
        }
        float wEA  = wA0 + wA1;
        float wEA8 = wA2 + wA3;
        float wEB  = wB0 + wB1;
        float wEB8 = wB2 + wB3;
        float2 cjA  = scj2[eloA];
        float2 cjA8 = scj2[ehiA];
        float2 cjB  = scj2[eloB];
        float2 cjB8 = scj2[ehiB];
        ax += wEA * (ci.x - cjA.x) + wEA8 * (ci.x - cjA8.x)
            + wEB * (ci.x - cjB.x) + wEB8 * (ci.x - cjB8.x);
        ay += wEA * (ci.y - cjA.y) + wEA8 * (ci.y - cjA8.y)
            + wEB * (ci.y - cjB.y) + wEB8 * (ci.y - cjB8.y);
    }

    // ---- warp reduce + node update ----
    #pragma unroll
    for (int off = 16; off > 0; off >>= 1) {
        ax += __shfl_down_sync(0xFFFFFFFFu, ax, off);
        ay += __shfl_down_sync(0xFFFFFFFFu, ay, off);
    }
    if (ln == 0) {
        float wv  = Wv[l * 3] + Wv[l * 3 + 1] + Wv[l * 3 + 2];
        float phi = fmaf(ti, wv, bv[l]);
        float vx = vin[(bb * NN + i) * 2];
        float vy = vin[(bb * NN + i) * 2 + 1];
        float nvx = fmaf(phi, vx, ax);
        float nvy = fmaf(phi, vy, ay);
        float ncx = ci.x + nvx;
        float ncy = ci.y + nvy;
        cout[(bb * NN + i) * 2]     = seluf(ncx);
        cout[(bb * NN + i) * 2 + 1] = seluf(ncy);
        vout[(bb * NN + i) * 2]     = seluf(nvx);
        vout[(bb * NN + i) * 2 + 1] = seluf(nvy);
    }
}

__global__ void egnn_head_kernel(const float* __restrict__ cin,
                                 const float* __restrict__ vin,
                                 const float* __restrict__ Wconv1,
                                 const float* __restrict__ bconv1,
                                 const float* __restrict__ Wconv2,
                                 const float* __restrict__ bconv2,
                                 float* __restrict__ out)
{
    int idx = blockIdx.x * blockDim.x + threadIdx.x;
    if (idx >= BB * NN) return;

    float x0 = seluf(cin[idx * 2]);
    float x1 = seluf(cin[idx * 2 + 1]);
    float x2 = seluf(vin[idx * 2]);
    float x3 = seluf(vin[idx * 2 + 1]);

    float y0 = bconv2[0], y1 = bconv2[1], y2 = bconv2[2], y3 = bconv2[3];
    #pragma unroll
    for (int o = 0; o < 32; o++) {
        float h = bconv1[o];
        h = fmaf(x0, Wconv1[o * 4 + 0], h);
        h = fmaf(x1, Wconv1[o * 4 + 1], h);
        h = fmaf(x2, Wconv1[o * 4 + 2], h);
        h = fmaf(x3, Wconv1[o * 4 + 3], h);
        h = seluf(h);
        y0 = fmaf(h, Wconv2[0 * 32 + o], y0);
        y1 = fmaf(h, Wconv2[1 * 32 + o], y1);
        y2 = fmaf(h, Wconv2[2 * 32 + o], y2);
        y3 = fmaf(h, Wconv2[3 * 32 + o], y3);
    }
    out[idx * 2]                   = y0;
    out[idx * 2 + 1]               = y1;
    out[BB * NN * 2 + idx * 2]     = y2;
    out[BB * NN * 2 + idx * 2 + 1] = y3;
}

extern "C" void kernel_launch(void* const* d_in, const int* in_sizes, int n_in,
                              void* d_out, int out_size)
{
    const float* t      = (const float*)d_in[0];
    const float* coors  = (const float*)d_in[1];
    const float* vel    = (const float*)d_in[2];
    const float* We1    = (const float*)d_in[3];
    const float* be1    = (const float*)d_in[4];
    const float* We2    = (const float*)d_in[5];
    const float* be2    = (const float*)d_in[6];
    const float* Wc1    = (const float*)d_in[7];
    const float* bc1    = (const float*)d_in[8];
    const float* Wc2    = (const float*)d_in[9];
    const float* bc2    = (const float*)d_in[10];
    const float* Wv     = (const float*)d_in[11];
    const float* bv     = (const float*)d_in[12];
    const float* Wconv1 = (const float*)d_in[13];
    const float* bconv1 = (const float*)d_in[14];
    const float* Wconv2 = (const float*)d_in[15];
    const float* bconv2 = (const float*)d_in[16];
    float* out = (float*)d_out;

    float *c0, *v0, *c1, *v1;
    cudaGetSymbolAddress((void**)&c0, g_c0);
    cudaGetSymbolAddress((void**)&v0, g_v0);
    cudaGetSymbolAddress((void**)&c1, g_c1);
    cudaGetSymbolAddress((void**)&v1, g_v1);

    dim3 grid(BB * 32);   // 2048 blocks: (batch, group of 4 i's), warp-per-i
    dim3 blk(128);
    egnn_layer_kernel<<<grid, blk>>>(t, coors, vel, c0, v0,
                                     We1, be1, We2, be2, Wc1, bc1, Wc2, bc2,
                                     Wv, bv, 0);
    egnn_layer_kernel<<<grid, blk>>>(t, c0, v0, c1, v1,
                                     We1, be1, We2, be2, Wc1, bc1, Wc2, bc2,
                                     Wv, bv, 1);
    egnn_head_kernel<<<(BB * NN + 127) / 128, 128>>>(c1, v1, Wconv1, bconv1,
                                                     Wconv2, bconv2, out);
}

// round 15
// speedup vs baseline: 1.1611x; 1.0298x over previous
#include <cuda_runtime.h>
#include <cuda_fp16.h>
#include <math.h>
#include <cstdint>

#define BB 64
#define NN 128
#define XS 9   // words per edge row in s_x1 (stride padding)

// scratch for intermediate coors/vel between layers (no allocs allowed)
__device__ float g_c0[BB*NN*2];
__device__ float g_v0[BB*NN*2];
__device__ float g_c1[BB*NN*2];
__device__ float g_v1[BB*NN*2];

union F2U { float2 f; unsigned long long u; };
union H2U { __half2 h; uint32_t u; };

__device__ __forceinline__ float2 ffma2(float2 a, float2 b, float2 c) {
    F2U A, B, C, R;
    A.f = a; B.f = b; C.f = c;
    asm("fma.rn.f32x2 %0, %1, %2, %3;" : "=l"(R.u) : "l"(A.u), "l"(B.u), "l"(C.u));
    return R.f;
}

// ---- packed f16x2 silu machinery ----
__device__ __forceinline__ uint32_t f2_to_h2(float2 v) {
    uint32_t r;
    asm("cvt.rn.f16x2.f32 %0, %1, %2;" : "=r"(r) : "f"(v.y), "f"(v.x));
    return r;
}
__device__ __forceinline__ uint32_t tanh_h2(uint32_t x) {
    uint32_t r;
    asm("tanh.approx.f16x2 %0, %1;" : "=r"(r) : "r"(x));
    return r;
}
__device__ __forceinline__ uint32_t hfma2u(uint32_t a, uint32_t b, uint32_t c) {
    H2U A, B, C, R;
    A.u = a; B.u = b; C.u = c;
    R.h = __hfma2(A.h, B.h, C.h);
    return R.u;
}
__device__ __forceinline__ uint32_t hmul2u(uint32_t a, uint32_t b) {
    H2U A, B, R;
    A.u = a; B.u = b;
    R.h = __hmul2(A.h, B.h);
    return R.u;
}
__device__ __forceinline__ uint32_t silu_h2_pre(uint32_t h) {
    return hfma2u(h, tanh_h2(h), h);
}
__device__ __forceinline__ uint32_t silu_h2(uint32_t x) {
    H2U half_c; half_c.h = __floats2half2_rn(0.5f, 0.5f);
    return silu_h2_pre(hmul2u(x, half_c.u));
}

__device__ __forceinline__ float seluf(float x) {
    const float scale = 1.0507009873554805f;
    const float alpha = 1.6732632423543772f;
    return x > 0.0f ? scale * x : scale * alpha * expm1f(x);
}

__device__ __forceinline__ uint32_t pack_h2s(float a, float b) {
    H2U c; c.h = __floats2half2_rn(a, b);
    return c.u;
}
__device__ __forceinline__ float h16res(float v) {
    return v - __half2float(__float2half_rn(v));
}

// mma.m16n8k16, f32 C/D (final Wc2 dot only)
__device__ __forceinline__ void mma16816c(float& d0, float& d1, float& d2, float& d3,
                                          uint32_t a0, uint32_t a1, uint32_t a2, uint32_t a3,
                                          uint32_t b0, uint32_t b1,
                                          float c0, float c1, float c2, float c3) {
    asm("mma.sync.aligned.m16n8k16.row.col.f32.f16.f16.f32 "
        "{%0,%1,%2,%3}, {%4,%5,%6,%7}, {%8,%9}, {%10,%11,%12,%13};"
        : "=f"(d0), "=f"(d1), "=f"(d2), "=f"(d3)
        : "r"(a0), "r"(a1), "r"(a2), "r"(a3), "r"(b0), "r"(b1),
          "f"(c0), "f"(c1), "f"(c2), "f"(c3));
}

// mma.m16n8k16, f16 C/D
__device__ __forceinline__ void mma16816h(uint32_t& d0, uint32_t& d1,
                                          uint32_t a0, uint32_t a1, uint32_t a2, uint32_t a3,
                                          uint32_t b0, uint32_t b1,
                                          uint32_t c0, uint32_t c1) {
    asm("mma.sync.aligned.m16n8k16.row.col.f16.f16.f16.f16 "
        "{%0,%1}, {%2,%3,%4,%5}, {%6,%7}, {%8,%9};"
        : "=r"(d0), "=r"(d1)
        : "r"(a0), "r"(a1), "r"(a2), "r"(a3), "r"(b0), "r"(b1),
          "r"(c0), "r"(c1));
}

__global__ __launch_bounds__(128, 5)
void egnn_layer_kernel(const float* __restrict__ t,
                       const float* __restrict__ cin,
                       const float* __restrict__ vin,
                       float* __restrict__ cout,
                       float* __restrict__ vout,
                       const float* __restrict__ We1,
                       const float* __restrict__ be1,
                       const float* __restrict__ We2,
                       const float* __restrict__ be2,
                       const float* __restrict__ Wc1,
                       const float* __restrict__ bc1,
                       const float* __restrict__ Wc2,
                       const float* __restrict__ bc2,
                       const float* __restrict__ Wv,
                       const float* __restrict__ bv,
                       int l)
{
    __shared__ float4 sUVp[8];          // {u2c,u2c1,v2c,v2c1} x0.5
    __shared__ float4 sWCp[8];          // {w2c,w2c1,(c+be1)2c,(c+be1)2c1} x0.5
    __shared__ uint32_t sbe2h[8];       // f16x2 {0.5be2 pair}
    __shared__ float  sWe2raw[256];     // 0.5*We2 [k*16+n]
    __shared__ float  sWc1raw[1024];    // 0.5*Wc1 [k*64+n]
    __shared__ uint32_t sbc1h[32];      // f16x2 {0.5bc1 pair}
    __shared__ float  sWc2s[64];        // Wc2 raw (f32)
    __shared__ float2 scj2[NN];
    __shared__ float  stj[NN];
    __shared__ uint32_t s_x1[4 * NN * XS];   // per-warp x1 tiles, f16x2 [edge][k-pair]
    // per-lane prepacked B fragments (same for all warps); [slot][ln], conflict-free
    __shared__ uint32_t s_fb2[4 * 32];   // We2 frags: (nt*2+half)*32+ln
    __shared__ uint32_t s_fb3[16 * 32];  // Wc1 frags: (nt*2+half)*32+ln
    __shared__ uint32_t s_fbd[8 * 32];   // Wc2-dot frags: (c*2+half)*32+ln

    const int tid   = threadIdx.x;
    const int wid   = tid >> 5;
    const int ln    = tid & 31;
    const int bb    = blockIdx.x >> 5;
    const int ibase = (blockIdx.x & 31) * 4;
    const int i     = ibase + wid;

    // ---- staging: raw weights ----
    const float* we1 = We1 + l * 128;
    if (tid < 8) {
        int c0 = 2 * tid, c1 = 2 * tid + 1;
        float u0 = 0.5f * (we1[c0] + we1[16 + c0] + we1[32 + c0]);
        float u1 = 0.5f * (we1[c1] + we1[16 + c1] + we1[32 + c1]);
        float v0 = 0.5f * (we1[48 + c0] + we1[64 + c0] + we1[80 + c0]);
        float v1 = 0.5f * (we1[48 + c1] + we1[64 + c1] + we1[80 + c1]);
        float w0 = 0.5f * we1[96 + c0];
        float w1 = 0.5f * we1[96 + c1];
        float k0 = 0.5f * (we1[112 + c0] + be1[l * 16 + c0]);
        float k1 = 0.5f * (we1[112 + c1] + be1[l * 16 + c1]);
        sUVp[tid] = make_float4(u0, u1, v0, v1);
        sWCp[tid] = make_float4(w0, w1, k0, k1);
        sbe2h[tid] = pack_h2s(0.5f * be2[l * 16 + c0], 0.5f * be2[l * 16 + c1]);
    } else if (tid < 40) {
        int k = tid - 8;
        sbc1h[k] = pack_h2s(0.5f * bc1[l * 64 + 2 * k], 0.5f * bc1[l * 64 + 2 * k + 1]);
    } else if (tid < 104) {
        sWc2s[tid - 40] = Wc2[l * 64 + tid - 40];
    }
    #pragma unroll
    for (int idx = tid; idx < 256; idx += 128)
        sWe2raw[idx] = 0.5f * We2[l * 256 + idx];
    #pragma unroll
    for (int idx = tid; idx < 1024; idx += 128)
        sWc1raw[idx] = 0.5f * Wc1[l * 1024 + idx];
    {
        const float2* c2 = (const float2*)(cin + bb * NN * 2);
        scj2[tid] = c2[tid];
        stj[tid]  = t[bb * NN + tid];
    }
    __syncthreads();

    const int p = ln & 3;
    const int g = ln >> 2;

    // ---- warp 0 prepacks per-lane B fragments into shared ----
    if (wid == 0) {
        #pragma unroll
        for (int nt = 0; nt < 2; ++nt) {
            int col = nt * 8 + g;
            s_fb2[(nt * 2 + 0) * 32 + ln] =
                pack_h2s(sWe2raw[(2 * p) * 16 + col],     sWe2raw[(2 * p + 1) * 16 + col]);
            s_fb2[(nt * 2 + 1) * 32 + ln] =
                pack_h2s(sWe2raw[(2 * p + 8) * 16 + col], sWe2raw[(2 * p + 9) * 16 + col]);
        }
        #pragma unroll
        for (int nt = 0; nt < 8; ++nt) {
            int col = nt * 8 + g;
            s_fb3[(nt * 2 + 0) * 32 + ln] =
                pack_h2s(sWc1raw[(2 * p) * 64 + col],     sWc1raw[(2 * p + 1) * 64 + col]);
            s_fb3[(nt * 2 + 1) * 32 + ln] =
                pack_h2s(sWc1raw[(2 * p + 8) * 64 + col], sWc1raw[(2 * p + 9) * 64 + col]);
        }
        #pragma unroll
        for (int c = 0; c < 4; ++c) {
            uint32_t lo = 0u, hi = 0u;
            if (g == 0) {
                lo = pack_h2s(sWc2s[16 * c + 2 * p],     sWc2s[16 * c + 2 * p + 1]);
                hi = pack_h2s(sWc2s[16 * c + 2 * p + 8], sWc2s[16 * c + 2 * p + 9]);
            } else if (g == 1) {
                lo = pack_h2s(h16res(sWc2s[16 * c + 2 * p]),
                              h16res(sWc2s[16 * c + 2 * p + 1]));
                hi = pack_h2s(h16res(sWc2s[16 * c + 2 * p + 8]),
                              h16res(sWc2s[16 * c + 2 * p + 9]));
            }
            s_fbd[(c * 2 + 0) * 32 + ln] = lo;
            s_fbd[(c * 2 + 1) * 32 + ln] = hi;
        }
    }

    const float ti  = stj[i];
    const float2 ci = scj2[i];
    const float2 ti2 = make_float2(ti, ti);
    const uint32_t be2h0 = sbe2h[p];
    const uint32_t be2h1 = sbe2h[p + 4];

    // ---- phase 1: x1 (f32 matvec, f16x2 silu) -> f16 edge-major shared ----
    uint32_t* sx = s_x1 + wid * NN * XS;
    #pragma unroll
    for (int ee = 0; ee < 4; ++ee) {
        const int e = ln + 32 * ee;
        const float tj = stj[e];
        const float2 cj = scj2[e];
        const float dx = ci.x - cj.x;
        const float dy = ci.y - cj.y;
        const float d = fmaf(dx, dx, dy * dy);
        const float2 tj2 = make_float2(tj, tj);
        const float2 d2  = make_float2(d, d);
        #pragma unroll
        for (int cp = 0; cp < 8; ++cp) {
            float4 uv = sUVp[cp];
            float4 wc = sWCp[cp];
            float2 h = ffma2(ti2, make_float2(uv.x, uv.y),
                      ffma2(tj2, make_float2(uv.z, uv.w),
                      ffma2(d2,  make_float2(wc.x, wc.y),
                                 make_float2(wc.z, wc.w))));
            sx[e * XS + cp] = silu_h2_pre(f2_to_h2(h));
        }
    }
    __syncthreads();   // fragments (warp 0) + own sx ready

    // MLP2 fragments: only 4 words, keep in regs
    const uint32_t b2f00 = s_fb2[0 * 32 + ln];
    const uint32_t b2f01 = s_fb2[1 * 32 + ln];
    const uint32_t b2f10 = s_fb2[2 * 32 + ln];
    const uint32_t b2f11 = s_fb2[3 * 32 + ln];

    // ---- phase 2: 4 iterations, 2 independent 16-edge tiles each (ILP) ----
    const float bc2c = (p == 0) ? bc2[l] : 0.0f;
    float ax = 0.0f, ay = 0.0f;

    #pragma unroll
    for (int rr = 0; rr < 4; ++rr) {
        const int eloA = 16 * rr + g;
        const int ehiA = eloA + 8;
        const int eloB = eloA + 64;
        const int ehiB = eloB + 8;

        uint32_t aA0 = sx[eloA * XS + p];
        uint32_t aA1 = sx[ehiA * XS + p];
        uint32_t aA2 = sx[eloA * XS + p + 4];
        uint32_t aA3 = sx[ehiA * XS + p + 4];
        uint32_t aB0 = sx[eloB * XS + p];
        uint32_t aB1 = sx[ehiB * XS + p];
        uint32_t aB2 = sx[eloB * XS + p + 4];
        uint32_t aB3 = sx[ehiB * XS + p + 4];

        // MLP2 both tiles
        uint32_t qA0, qA1, qA2, qA3, qB0, qB1, qB2, qB3;
        {
            uint32_t DA0, DA1, DA2, DA3, DB0, DB1, DB2, DB3;
            mma16816h(DA0, DA1, aA0, aA1, aA2, aA3, b2f00, b2f01, be2h0, be2h0);
            mma16816h(DB0, DB1, aB0, aB1, aB2, aB3, b2f00, b2f01, be2h0, be2h0);
            mma16816h(DA2, DA3, aA0, aA1, aA2, aA3, b2f10, b2f11, be2h1, be2h1);
            mma16816h(DB2, DB3, aB0, aB1, aB2, aB3, b2f10, b2f11, be2h1, be2h1);
            qA0 = silu_h2(silu_h2_pre(DA0));
            qB0 = silu_h2(silu_h2_pre(DB0));
            qA1 = silu_h2(silu_h2_pre(DA1));
            qB1 = silu_h2(silu_h2_pre(DB1));
            qA2 = silu_h2(silu_h2_pre(DA2));
            qB2 = silu_h2(silu_h2_pre(DB2));
            qA3 = silu_h2(silu_h2_pre(DA3));
            qB3 = silu_h2(silu_h2_pre(DB3));
        }

        // MLP3 + dot, both tiles interleaved; weight frags loaded from shared
        float wA0 = bc2c, wA1 = 0.0f, wA2 = bc2c, wA3 = 0.0f;
        float wB0 = bc2c, wB1 = 0.0f, wB2 = bc2c, wB3 = 0.0f;
        #pragma unroll
        for (int c = 0; c < 4; ++c) {
            uint32_t bfa0 = s_fb3[(4 * c + 0) * 32 + ln];   // nt=2c half0
            uint32_t bfa1 = s_fb3[(4 * c + 1) * 32 + ln];   // nt=2c half1
            uint32_t bfb0 = s_fb3[(4 * c + 2) * 32 + ln];   // nt=2c+1 half0
            uint32_t bfb1 = s_fb3[(4 * c + 3) * 32 + ln];   // nt=2c+1 half1
            uint32_t bdl  = s_fbd[(2 * c + 0) * 32 + ln];
            uint32_t bdh  = s_fbd[(2 * c + 1) * 32 + ln];
            uint32_t bb0 = sbc1h[4 * (2 * c) + p];
            uint32_t bb1 = sbc1h[4 * (2 * c + 1) + p];
            uint32_t DA0, DA1, EA0, EA1, DB0, DB1, EB0, EB1;
            mma16816h(DA0, DA1, qA0, qA1, qA2, qA3, bfa0, bfa1, bb0, bb0);
            mma16816h(DB0, DB1, qB0, qB1, qB2, qB3, bfa0, bfa1, bb0, bb0);
            mma16816h(EA0, EA1, qA0, qA1, qA2, qA3, bfb0, bfb1, bb1, bb1);
            mma16816h(EB0, EB1, qB0, qB1, qB2, qB3, bfb0, bfb1, bb1, bb1);
            uint32_t hA0 = silu_h2_pre(DA0);
            uint32_t hB0 = silu_h2_pre(DB0);
            uint32_t hA1 = silu_h2_pre(DA1);
            uint32_t hB1 = silu_h2_pre(DB1);
            uint32_t hA2 = silu_h2_pre(EA0);
            uint32_t hB2 = silu_h2_pre(EB0);
            uint32_t hA3 = silu_h2_pre(EA1);
            uint32_t hB3 = silu_h2_pre(EB1);
            mma16816c(wA0, wA1, wA2, wA3, hA0, hA1, hA2, hA3, bdl, bdh,
                      wA0, wA1, wA2, wA3);
            mma16816c(wB0, wB1, wB2, wB3, hB0, hB1, hB2, hB3, bdl, bdh,
                      wB0, wB1, wB2, wB3);
        }
        float wEA  = wA0 + wA1;
        float wEA8 = wA2 + wA3;
        float wEB  = wB0 + wB1;
        float wEB8 = wB2 + wB3;
        float2 cjA  = scj2[eloA];
        float2 cjA8 = scj2[ehiA];
        float2 cjB  = scj2[eloB];
        float2 cjB8 = scj2[ehiB];
        ax += wEA * (ci.x - cjA.x) + wEA8 * (ci.x - cjA8.x)
            + wEB * (ci.x - cjB.x) + wEB8 * (ci.x - cjB8.x);
        ay += wEA * (ci.y - cjA.y) + wEA8 * (ci.y - cjA8.y)
            + wEB * (ci.y - cjB.y) + wEB8 * (ci.y - cjB8.y);
    }

    // ---- warp reduce + node update ----
    #pragma unroll
    for (int off = 16; off > 0; off >>= 1) {
        ax += __shfl_down_sync(0xFFFFFFFFu, ax, off);
        ay += __shfl_down_sync(0xFFFFFFFFu, ay, off);
    }
    if (ln == 0) {
        float wv  = Wv[l * 3] + Wv[l * 3 + 1] + Wv[l * 3 + 2];
        float phi = fmaf(ti, wv, bv[l]);
        float vx = vin[(bb * NN + i) * 2];
        float vy = vin[(bb * NN + i) * 2 + 1];
        float nvx = fmaf(phi, vx, ax);
        float nvy = fmaf(phi, vy, ay);
        float ncx = ci.x + nvx;
        float ncy = ci.y + nvy;
        cout[(bb * NN + i) * 2]     = seluf(ncx);
        cout[(bb * NN + i) * 2 + 1] = seluf(ncy);
        vout[(bb * NN + i) * 2]     = seluf(nvx);
        vout[(bb * NN + i) * 2 + 1] = seluf(nvy);
    }
}

__global__ void egnn_head_kernel(const float* __restrict__ cin,
                                 const float* __restrict__ vin,
                                 const float* __restrict__ Wconv1,
                                 const float* __restrict__ bconv1,
                                 const float* __restrict__ Wconv2,
                                 const float* __restrict__ bconv2,
                                 float* __restrict__ out)
{
    int idx = blockIdx.x * blockDim.x + threadIdx.x;
    if (idx >= BB * NN) return;

    float x0 = seluf(cin[idx * 2]);
    float x1 = seluf(cin[idx * 2 + 1]);
    float x2 = seluf(vin[idx * 2]);
    float x3 = seluf(vin[idx * 2 + 1]);

    float y0 = bconv2[0], y1 = bconv2[1], y2 = bconv2[2], y3 = bconv2[3];
    #pragma unroll
    for (int o = 0; o < 32; o++) {
        float h = bconv1[o];
        h = fmaf(x0, Wconv1[o * 4 + 0], h);
        h = fmaf(x1, Wconv1[o * 4 + 1], h);
        h = fmaf(x2, Wconv1[o * 4 + 2], h);
        h = fmaf(x3, Wconv1[o * 4 + 3], h);
        h = seluf(h);
        y0 = fmaf(h, Wconv2[0 * 32 + o], y0);
        y1 = fmaf(h, Wconv2[1 * 32 + o], y1);
        y2 = fmaf(h, Wconv2[2 * 32 + o], y2);
        y3 = fmaf(h, Wconv2[3 * 32 + o], y3);
    }
    out[idx * 2]                   = y0;
    out[idx * 2 + 1]               = y1;
    out[BB * NN * 2 + idx * 2]     = y2;
    out[BB * NN * 2 + idx * 2 + 1] = y3;
}

extern "C" void kernel_launch(void* const* d_in, const int* in_sizes, int n_in,
                              void* d_out, int out_size)
{
    const float* t      = (const float*)d_in[0];
    const float* coors  = (const float*)d_in[1];
    const float* vel    = (const float*)d_in[2];
    const float* We1    = (const float*)d_in[3];
    const float* be1    = (const float*)d_in[4];
    const float* We2    = (const float*)d_in[5];
    const float* be2    = (const float*)d_in[6];
    const float* Wc1    = (const float*)d_in[7];
    const float* bc1    = (const float*)d_in[8];
    const float* Wc2    = (const float*)d_in[9];
    const float* bc2    = (const float*)d_in[10];
    const float* Wv     = (const float*)d_in[11];
    const float* bv     = (const float*)d_in[12];
    const float* Wconv1 = (const float*)d_in[13];
    const float* bconv1 = (const float*)d_in[14];
    const float* Wconv2 = (const float*)d_in[15];
    const float* bconv2 = (const float*)d_in[16];
    float* out = (float*)d_out;

    float *c0, *v0, *c1, *v1;
    cudaGetSymbolAddress((void**)&c0, g_c0);
    cudaGetSymbolAddress((void**)&v0, g_v0);
    cudaGetSymbolAddress((void**)&c1, g_c1);
    cudaGetSymbolAddress((void**)&v1, g_v1);

    dim3 grid(BB * 32);   // 2048 blocks: (batch, group of 4 i's), warp-per-i
    dim3 blk(128);
    egnn_layer_kernel<<<grid, blk>>>(t, coors, vel, c0, v0,
                                     We1, be1, We2, be2, Wc1, bc1, Wc2, bc2,
                                     Wv, bv, 0);
    egnn_layer_kernel<<<grid, blk>>>(t, c0, v0, c1, v1,
                                     We1, be1, We2, be2, Wc1, bc1, Wc2, bc2,
                                     Wv, bv, 1);
    egnn_head_kernel<<<(BB * NN + 127) / 128, 128>>>(c1, v1, Wconv1, bconv1,
                                                     Wconv2, bconv2, out);
}